// round 2
// baseline (speedup 1.0000x reference)
#include <cuda_runtime.h>
#include <cuda_bf16.h>

#define D 128
#define OUTD 128
#define MAXN 100000
#define EPS 0.1f

// Scratch (allocation-free rule: __device__ globals)
__device__ float g_agg[(size_t)MAXN * D];
__device__ float g_alpha_l[MAXN];
__device__ float g_alpha_r[MAXN];
__device__ int   g_is64;

// ---------------------------------------------------------------------------
// Kernel 0: detect whether edge_index is int64 or int32.
// int64 values < 2^31 store as [low32, 0] pairs -> all odd words zero.
// ---------------------------------------------------------------------------
__global__ void detect_kernel(const unsigned int* __restrict__ ei_words, int E) {
    int nchk = 128;
    if (2 * nchk > 2 * E) nchk = E;
    int all_odd_zero = 1;
    for (int k = 0; k < nchk; k++) {
        if (ei_words[2 * k + 1] != 0u) { all_odd_zero = 0; break; }
    }
    g_is64 = all_odd_zero;
}

// ---------------------------------------------------------------------------
// Kernel 1: per-node attention logits + agg = EPS * x_0
// one warp per node; lane handles one float4 (32*4 = 128 = D)
// ---------------------------------------------------------------------------
__global__ void alpha_init_kernel(const float* __restrict__ x,
                                  const float* __restrict__ x0,
                                  const float* __restrict__ att_l,
                                  const float* __restrict__ att_r,
                                  int N) {
    int warp = (blockIdx.x * blockDim.x + threadIdx.x) >> 5;
    int lane = threadIdx.x & 31;
    if (warp >= N) return;

    float4 xv = reinterpret_cast<const float4*>(x + (size_t)warp * D)[lane];
    float4 al = reinterpret_cast<const float4*>(att_l)[lane];
    float4 ar = reinterpret_cast<const float4*>(att_r)[lane];

    float sl = xv.x * al.x + xv.y * al.y + xv.z * al.z + xv.w * al.w;
    float sr = xv.x * ar.x + xv.y * ar.y + xv.z * ar.z + xv.w * ar.w;
#pragma unroll
    for (int o = 16; o > 0; o >>= 1) {
        sl += __shfl_xor_sync(0xffffffffu, sl, o);
        sr += __shfl_xor_sync(0xffffffffu, sr, o);
    }
    if (lane == 0) {
        g_alpha_l[warp] = sl;
        g_alpha_r[warp] = sr;
    }

    float4 x0v = reinterpret_cast<const float4*>(x0 + (size_t)warp * D)[lane];
    float4 outv = make_float4(EPS * x0v.x, EPS * x0v.y, EPS * x0v.z, EPS * x0v.w);
    reinterpret_cast<float4*>(g_agg + (size_t)warp * D)[lane] = outv;
}

// ---------------------------------------------------------------------------
// Kernel 2: per-edge gather + scatter-add
// one warp per edge; coeff = tanh(alpha_l[src] + alpha_r[dst]) * w_e
// vectorized reduction: red.global.add.v4.f32 (sm_90+)
// ---------------------------------------------------------------------------
__global__ void scatter_kernel(const float* __restrict__ x,
                               const void* __restrict__ ei_raw,
                               const float* __restrict__ ew,
                               int E) {
    int warp = (blockIdx.x * blockDim.x + threadIdx.x) >> 5;
    int lane = threadIdx.x & 31;
    if (warp >= E) return;

    int src = 0, dst = 0;
    float c = 0.f;
    if (lane == 0) {
        if (g_is64) {
            const long long* ei = (const long long*)ei_raw;
            src = (int)ei[warp];
            dst = (int)ei[(size_t)E + warp];
        } else {
            const int* ei = (const int*)ei_raw;
            src = ei[warp];
            dst = ei[(size_t)E + warp];
        }
        c = tanhf(g_alpha_l[src] + g_alpha_r[dst]) * ew[warp];
    }
    src = __shfl_sync(0xffffffffu, src, 0);
    dst = __shfl_sync(0xffffffffu, dst, 0);
    c   = __shfl_sync(0xffffffffu, c, 0);

    float4 xv = reinterpret_cast<const float4*>(x + (size_t)src * D)[lane];
    float* p = g_agg + (size_t)dst * D + lane * 4;
    asm volatile("red.global.add.v4.f32 [%0], {%1, %2, %3, %4};"
                 :: "l"(p), "f"(xv.x * c), "f"(xv.y * c), "f"(xv.z * c), "f"(xv.w * c)
                 : "memory");
}

// ---------------------------------------------------------------------------
// Kernel 3: out = relu(agg) @ W^T + b
// block tile: 128 rows x 128 cols, K chunks of 16; 256 threads, 8x8 microtile
// ---------------------------------------------------------------------------
__global__ void gemm_kernel(const float* __restrict__ W,
                            const float* __restrict__ bias,
                            float* __restrict__ out,
                            int N) {
    __shared__ float As[16][128];  // [k][m], relu applied at load
    __shared__ float Bs[16][128];  // [k][o] = W[o][k]

    int m0 = blockIdx.x * 128;
    int tid = threadIdx.x;        // 0..255
    int tx = tid & 15;            // col group
    int ty = tid >> 4;            // row group

    float acc[8][8];
#pragma unroll
    for (int i = 0; i < 8; i++)
#pragma unroll
        for (int j = 0; j < 8; j++) acc[i][j] = 0.f;

    for (int kc = 0; kc < D; kc += 16) {
        // load A tile (relu): thread -> row r = tid/2, 8 consecutive k
        {
            int r = tid >> 1;
            int k8 = (tid & 1) * 8;
            int row = m0 + r;
            float4 v0, v1;
            if (row < N) {
                const float4* p = reinterpret_cast<const float4*>(
                    g_agg + (size_t)row * D + kc + k8);
                v0 = p[0];
                v1 = p[1];
            } else {
                v0 = make_float4(0, 0, 0, 0);
                v1 = make_float4(0, 0, 0, 0);
            }
            As[k8 + 0][r] = fmaxf(v0.x, 0.f);
            As[k8 + 1][r] = fmaxf(v0.y, 0.f);
            As[k8 + 2][r] = fmaxf(v0.z, 0.f);
            As[k8 + 3][r] = fmaxf(v0.w, 0.f);
            As[k8 + 4][r] = fmaxf(v1.x, 0.f);
            As[k8 + 5][r] = fmaxf(v1.y, 0.f);
            As[k8 + 6][r] = fmaxf(v1.z, 0.f);
            As[k8 + 7][r] = fmaxf(v1.w, 0.f);
        }
        // load W tile: thread -> out col o = tid/2, 8 consecutive k
        {
            int o = tid >> 1;
            int k8 = (tid & 1) * 8;
            const float4* p = reinterpret_cast<const float4*>(
                W + (size_t)o * D + kc + k8);
            float4 v0 = p[0];
            float4 v1 = p[1];
            Bs[k8 + 0][o] = v0.x;
            Bs[k8 + 1][o] = v0.y;
            Bs[k8 + 2][o] = v0.z;
            Bs[k8 + 3][o] = v0.w;
            Bs[k8 + 4][o] = v1.x;
            Bs[k8 + 5][o] = v1.y;
            Bs[k8 + 6][o] = v1.z;
            Bs[k8 + 7][o] = v1.w;
        }
        __syncthreads();

#pragma unroll
        for (int kk = 0; kk < 16; kk++) {
            float a[8], bb[8];
#pragma unroll
            for (int i = 0; i < 8; i++) a[i] = As[kk][ty * 8 + i];
#pragma unroll
            for (int j = 0; j < 8; j++) bb[j] = Bs[kk][tx * 8 + j];
#pragma unroll
            for (int i = 0; i < 8; i++)
#pragma unroll
                for (int j = 0; j < 8; j++) acc[i][j] = fmaf(a[i], bb[j], acc[i][j]);
        }
        __syncthreads();
    }

    // epilogue: + bias, store
    float bv[8];
#pragma unroll
    for (int j = 0; j < 8; j++) bv[j] = bias[tx * 8 + j];

#pragma unroll
    for (int i = 0; i < 8; i++) {
        int row = m0 + ty * 8 + i;
        if (row < N) {
            float4 o0 = make_float4(acc[i][0] + bv[0], acc[i][1] + bv[1],
                                    acc[i][2] + bv[2], acc[i][3] + bv[3]);
            float4 o1 = make_float4(acc[i][4] + bv[4], acc[i][5] + bv[5],
                                    acc[i][6] + bv[6], acc[i][7] + bv[7]);
            float4* p = reinterpret_cast<float4*>(out + (size_t)row * OUTD + tx * 8);
            p[0] = o0;
            p[1] = o1;
        }
    }
}

// ---------------------------------------------------------------------------
// Launch
// inputs: 0 x [N,128], 1 x_0 [N,128], 2 edge_weight [E], 3 att_l [128],
//         4 att_r [128], 5 W [128,128], 6 b [128], 7 edge_index [2,E]
// ---------------------------------------------------------------------------
extern "C" void kernel_launch(void* const* d_in, const int* in_sizes, int n_in,
                              void* d_out, int out_size) {
    const float* x      = (const float*)d_in[0];
    const float* x0     = (const float*)d_in[1];
    const float* ew     = (const float*)d_in[2];
    const float* att_l  = (const float*)d_in[3];
    const float* att_r  = (const float*)d_in[4];
    const float* W      = (const float*)d_in[5];
    const float* bias   = (const float*)d_in[6];
    const void*  ei     = (const void*)d_in[7];
    float* out = (float*)d_out;

    int N = in_sizes[1] / D;
    int E = in_sizes[2];

    // K0: dtype detection for edge_index (int32 vs int64).
    detect_kernel<<<1, 1>>>((const unsigned int*)ei, E);

    // K1: alpha + agg init. 8 warps/block.
    {
        int blocks = (N + 7) / 8;
        alpha_init_kernel<<<blocks, 256>>>(x, x0, att_l, att_r, N);
    }
    // K2: edge scatter. 8 warps/block, 1 warp per edge.
    {
        int blocks = (E + 7) / 8;
        scatter_kernel<<<blocks, 256>>>(x, ei, ew, E);
    }
    // K3: GEMM epilogue.
    {
        int blocks = (N + 127) / 128;
        gemm_kernel<<<blocks, 256>>>(W, bias, out, N);
    }
}

// round 3
// speedup vs baseline: 1.3612x; 1.3612x over previous
#include <cuda_runtime.h>
#include <cuda_bf16.h>
#include <cstdint>

#define D 128
#define OUTD 128
#define MAXN 100000
#define EPS 0.1f

// Scratch (allocation-free rule: __device__ globals)
__device__ float g_agg[(size_t)MAXN * D];
__device__ float g_alpha_l[MAXN];
__device__ float g_alpha_r[MAXN];
__device__ int   g_is64;

// ---------------------------------------------------------------------------
// Kernel 0: detect whether edge_index is int64 or int32.
// int64 values < 2^31 store as [low32, 0] pairs -> all odd words zero.
// ---------------------------------------------------------------------------
__global__ void detect_kernel(const unsigned int* __restrict__ ei_words, int E) {
    int nchk = 128;
    if (nchk > E) nchk = E;
    int all_odd_zero = 1;
    for (int k = 0; k < nchk; k++) {
        if (ei_words[2 * k + 1] != 0u) { all_odd_zero = 0; break; }
    }
    g_is64 = all_odd_zero;
}

// ---------------------------------------------------------------------------
// Kernel 1: per-node attention logits + agg = EPS * x_0
// ---------------------------------------------------------------------------
__global__ void alpha_init_kernel(const float* __restrict__ x,
                                  const float* __restrict__ x0,
                                  const float* __restrict__ att_l,
                                  const float* __restrict__ att_r,
                                  int N) {
    int warp = (blockIdx.x * blockDim.x + threadIdx.x) >> 5;
    int lane = threadIdx.x & 31;
    if (warp >= N) return;

    float4 xv = reinterpret_cast<const float4*>(x + (size_t)warp * D)[lane];
    float4 al = reinterpret_cast<const float4*>(att_l)[lane];
    float4 ar = reinterpret_cast<const float4*>(att_r)[lane];

    float sl = xv.x * al.x + xv.y * al.y + xv.z * al.z + xv.w * al.w;
    float sr = xv.x * ar.x + xv.y * ar.y + xv.z * ar.z + xv.w * ar.w;
#pragma unroll
    for (int o = 16; o > 0; o >>= 1) {
        sl += __shfl_xor_sync(0xffffffffu, sl, o);
        sr += __shfl_xor_sync(0xffffffffu, sr, o);
    }
    if (lane == 0) {
        g_alpha_l[warp] = sl;
        g_alpha_r[warp] = sr;
    }

    float4 x0v = reinterpret_cast<const float4*>(x0 + (size_t)warp * D)[lane];
    float4 outv = make_float4(EPS * x0v.x, EPS * x0v.y, EPS * x0v.z, EPS * x0v.w);
    reinterpret_cast<float4*>(g_agg + (size_t)warp * D)[lane] = outv;
}

// ---------------------------------------------------------------------------
// Kernel 2: per-edge gather + scatter-add.
// One warp handles 32 edges: lane e loads its own edge metadata (coalesced),
// then shfl-broadcast loop does the vectorized gather + red.global.add.v4.
// ---------------------------------------------------------------------------
__global__ void scatter_kernel(const float* __restrict__ x,
                               const void* __restrict__ ei_raw,
                               const float* __restrict__ ew,
                               int E) {
    int warp = (blockIdx.x * blockDim.x + threadIdx.x) >> 5;
    int lane = threadIdx.x & 31;
    int base = warp * 32;
    if (base >= E) return;

    int e = base + lane;
    int src = 0, dst = 0;
    float c = 0.f;
    if (e < E) {
        if (g_is64) {
            const long long* ei = (const long long*)ei_raw;
            src = (int)ei[e];
            dst = (int)ei[(size_t)E + e];
        } else {
            const int* ei = (const int*)ei_raw;
            src = ei[e];
            dst = ei[(size_t)E + e];
        }
        c = tanhf(g_alpha_l[src] + g_alpha_r[dst]) * ew[e];
    }

    int nvalid = E - base;
    if (nvalid > 32) nvalid = 32;
    for (int j = 0; j < nvalid; j++) {
        int s   = __shfl_sync(0xffffffffu, src, j);
        int d   = __shfl_sync(0xffffffffu, dst, j);
        float cc = __shfl_sync(0xffffffffu, c, j);
        float4 xv = reinterpret_cast<const float4*>(x + (size_t)s * D)[lane];
        float* p = g_agg + (size_t)d * D + lane * 4;
        asm volatile("red.global.add.v4.f32 [%0], {%1, %2, %3, %4};"
                     :: "l"(p), "f"(xv.x * cc), "f"(xv.y * cc),
                        "f"(xv.z * cc), "f"(xv.w * cc)
                     : "memory");
    }
}

// ---------------------------------------------------------------------------
// Kernel 3: out = relu(agg) @ W^T + b  via 3xTF32 mma.sync (fp32 accuracy)
// block: 256 threads, tile M=128 x N=128, K chunks of 16.
// warp grid 4x2: warpM in 0..3 (32 rows), warpN in 0..1 (64 cols).
// per warp: 2 m16 tiles x 8 n8 tiles, mma.m16n8k8.tf32, 3-way split.
// ---------------------------------------------------------------------------
#define KPAD 20  // 16 + 4 pad: fragment LDS patterns are bank-conflict-free

__device__ __forceinline__ uint32_t f2tf32(float f) {
    uint32_t r;
    asm("cvt.rna.tf32.f32 %0, %1;" : "=r"(r) : "f"(f));
    return r;
}

__device__ __forceinline__ void mma_tf32(float* d, const uint32_t* a, const uint32_t* b) {
    asm volatile(
        "mma.sync.aligned.m16n8k8.row.col.f32.tf32.tf32.f32 "
        "{%0,%1,%2,%3}, {%4,%5,%6,%7}, {%8,%9}, {%0,%1,%2,%3};"
        : "+f"(d[0]), "+f"(d[1]), "+f"(d[2]), "+f"(d[3])
        : "r"(a[0]), "r"(a[1]), "r"(a[2]), "r"(a[3]), "r"(b[0]), "r"(b[1]));
}

__global__ __launch_bounds__(256)
void gemm_kernel(const float* __restrict__ W,
                 const float* __restrict__ bias,
                 float* __restrict__ out,
                 int N) {
    __shared__ uint32_t As_hi[128 * KPAD];
    __shared__ uint32_t As_lo[128 * KPAD];
    __shared__ uint32_t Ws_hi[128 * KPAD];
    __shared__ uint32_t Ws_lo[128 * KPAD];

    int m0 = blockIdx.x * 128;
    int tid = threadIdx.x;
    int lane = tid & 31;
    int wid = tid >> 5;
    int warpM = wid >> 1;   // 0..3
    int warpN = wid & 1;    // 0..1

    float acc[2][8][4];
#pragma unroll
    for (int mt = 0; mt < 2; mt++)
#pragma unroll
        for (int nt = 0; nt < 8; nt++)
#pragma unroll
            for (int i = 0; i < 4; i++) acc[mt][nt][i] = 0.f;

    int fr = tid >> 1;             // fill row 0..127

    for (int kc = 0; kc < D; kc += 16) {
        // ---- fill smem: relu(A) and W, split into tf32 hi/lo ----
#pragma unroll
        for (int i = 0; i < 2; i++) {
            int f4 = (tid & 1) * 2 + i;  // 0..3
            int kk = f4 * 4;
            // A
            float4 v;
            int row = m0 + fr;
            if (row < N) {
                v = *reinterpret_cast<const float4*>(g_agg + (size_t)row * D + kc + kk);
            } else {
                v = make_float4(0.f, 0.f, 0.f, 0.f);
            }
            float a0 = fmaxf(v.x, 0.f), a1 = fmaxf(v.y, 0.f);
            float a2 = fmaxf(v.z, 0.f), a3 = fmaxf(v.w, 0.f);
            uint32_t h0 = f2tf32(a0), h1 = f2tf32(a1), h2 = f2tf32(a2), h3 = f2tf32(a3);
            As_hi[fr * KPAD + kk + 0] = h0;
            As_hi[fr * KPAD + kk + 1] = h1;
            As_hi[fr * KPAD + kk + 2] = h2;
            As_hi[fr * KPAD + kk + 3] = h3;
            As_lo[fr * KPAD + kk + 0] = f2tf32(a0 - __uint_as_float(h0));
            As_lo[fr * KPAD + kk + 1] = f2tf32(a1 - __uint_as_float(h1));
            As_lo[fr * KPAD + kk + 2] = f2tf32(a2 - __uint_as_float(h2));
            As_lo[fr * KPAD + kk + 3] = f2tf32(a3 - __uint_as_float(h3));
            // W
            float4 w = *reinterpret_cast<const float4*>(W + (size_t)fr * D + kc + kk);
            uint32_t g0 = f2tf32(w.x), g1 = f2tf32(w.y), g2 = f2tf32(w.z), g3 = f2tf32(w.w);
            Ws_hi[fr * KPAD + kk + 0] = g0;
            Ws_hi[fr * KPAD + kk + 1] = g1;
            Ws_hi[fr * KPAD + kk + 2] = g2;
            Ws_hi[fr * KPAD + kk + 3] = g3;
            Ws_lo[fr * KPAD + kk + 0] = f2tf32(w.x - __uint_as_float(g0));
            Ws_lo[fr * KPAD + kk + 1] = f2tf32(w.y - __uint_as_float(g1));
            Ws_lo[fr * KPAD + kk + 2] = f2tf32(w.z - __uint_as_float(g2));
            Ws_lo[fr * KPAD + kk + 3] = f2tf32(w.w - __uint_as_float(g3));
        }
        __syncthreads();

        // ---- compute: 2 k-steps of 8 ----
#pragma unroll
        for (int ks = 0; ks < 2; ks++) {
            int c = ks * 8 + (lane & 3);
            uint32_t ahi[2][4], alo[2][4];
#pragma unroll
            for (int mt = 0; mt < 2; mt++) {
                int r = warpM * 32 + mt * 16 + (lane >> 2);
                ahi[mt][0] = As_hi[r * KPAD + c];
                ahi[mt][1] = As_hi[(r + 8) * KPAD + c];
                ahi[mt][2] = As_hi[r * KPAD + c + 4];
                ahi[mt][3] = As_hi[(r + 8) * KPAD + c + 4];
                alo[mt][0] = As_lo[r * KPAD + c];
                alo[mt][1] = As_lo[(r + 8) * KPAD + c];
                alo[mt][2] = As_lo[r * KPAD + c + 4];
                alo[mt][3] = As_lo[(r + 8) * KPAD + c + 4];
            }
            uint32_t bhi[8][2], blo[8][2];
#pragma unroll
            for (int nt = 0; nt < 8; nt++) {
                int n = warpN * 64 + nt * 8 + (lane >> 2);
                bhi[nt][0] = Ws_hi[n * KPAD + c];
                bhi[nt][1] = Ws_hi[n * KPAD + c + 4];
                blo[nt][0] = Ws_lo[n * KPAD + c];
                blo[nt][1] = Ws_lo[n * KPAD + c + 4];
            }
#pragma unroll
            for (int mt = 0; mt < 2; mt++)
#pragma unroll
                for (int nt = 0; nt < 8; nt++) {
                    mma_tf32(acc[mt][nt], ahi[mt], blo[nt]);
                    mma_tf32(acc[mt][nt], alo[mt], bhi[nt]);
                    mma_tf32(acc[mt][nt], ahi[mt], bhi[nt]);
                }
        }
        __syncthreads();
    }

    // ---- epilogue: + bias, store ----
#pragma unroll
    for (int mt = 0; mt < 2; mt++) {
        int r0 = m0 + warpM * 32 + mt * 16 + (lane >> 2);
#pragma unroll
        for (int nt = 0; nt < 8; nt++) {
            int col = warpN * 64 + nt * 8 + (lane & 3) * 2;
            float b0 = bias[col], b1 = bias[col + 1];
            if (r0 < N) {
                float2 v = make_float2(acc[mt][nt][0] + b0, acc[mt][nt][1] + b1);
                *reinterpret_cast<float2*>(out + (size_t)r0 * OUTD + col) = v;
            }
            if (r0 + 8 < N) {
                float2 v = make_float2(acc[mt][nt][2] + b0, acc[mt][nt][3] + b1);
                *reinterpret_cast<float2*>(out + (size_t)(r0 + 8) * OUTD + col) = v;
            }
        }
    }
}

// ---------------------------------------------------------------------------
// Launch
// inputs: 0 x [N,128], 1 x_0 [N,128], 2 edge_weight [E], 3 att_l [128],
//         4 att_r [128], 5 W [128,128], 6 b [128], 7 edge_index [2,E]
// ---------------------------------------------------------------------------
extern "C" void kernel_launch(void* const* d_in, const int* in_sizes, int n_in,
                              void* d_out, int out_size) {
    const float* x      = (const float*)d_in[0];
    const float* x0     = (const float*)d_in[1];
    const float* ew     = (const float*)d_in[2];
    const float* att_l  = (const float*)d_in[3];
    const float* att_r  = (const float*)d_in[4];
    const float* W      = (const float*)d_in[5];
    const float* bias   = (const float*)d_in[6];
    const void*  ei     = (const void*)d_in[7];
    float* out = (float*)d_out;

    int N = in_sizes[1] / D;
    int E = in_sizes[2];

    detect_kernel<<<1, 1>>>((const unsigned int*)ei, E);

    {
        int blocks = (N + 7) / 8;
        alpha_init_kernel<<<blocks, 256>>>(x, x0, att_l, att_r, N);
    }
    {
        int warps = (E + 31) / 32;
        int blocks = (warps + 7) / 8;
        scatter_kernel<<<blocks, 256>>>(x, ei, ew, E);
    }
    {
        int blocks = (N + 127) / 128;
        gemm_kernel<<<blocks, 256>>>(W, bias, out, N);
    }
}